// round 7
// baseline (speedup 1.0000x reference)
#include <cuda_runtime.h>
#include <cuda_bf16.h>

// ---------------- problem constants ----------------
constexpr int L_  = 4;
constexpr int CB_ = 256;
constexpr int D_  = 512;
constexpr int B_  = 16;
constexpr int T_  = 4096;
constexpr int N_BT = B_ * T_;          // 65536 samples per channel for BN
constexpr float EPS_ = 1e-5f;

// ---------------- device scratch (no allocs allowed) ----------------
__device__ float g_xbuf[(size_t)B_ * CB_ * T_];   // 64 MiB  (inter-layer x)
__device__ float g_z1[(size_t)B_ * D_ * T_];      // 128 MiB (post conv1/prelu)
__device__ float g_z2[(size_t)B_ * D_ * T_];      // 128 MiB (post dwconv/prelu)
__device__ __align__(16) __nv_bfloat16 g_w1s[L_ * D_ * CB_];  // sign weights +-1
__device__ __align__(16) __nv_bfloat16 g_w2s[L_ * CB_ * D_];
__device__ float g_wds[L_ * D_ * 3];
__device__ float g_sum[D_];
__device__ float g_sumsq[D_];
__device__ float g_scale[D_];
__device__ float g_shift[D_];

// ---------------- PTX helpers ----------------
__device__ __forceinline__ unsigned smem_u32(const void* p) {
    return (unsigned)__cvta_generic_to_shared(p);
}
__device__ __forceinline__ void ldsm4(unsigned* r, const void* p) {
    unsigned a = smem_u32(p);
    asm volatile("ldmatrix.sync.aligned.m8n8.x4.shared.b16 {%0,%1,%2,%3}, [%4];"
                 : "=r"(r[0]), "=r"(r[1]), "=r"(r[2]), "=r"(r[3]) : "r"(a));
}
__device__ __forceinline__ void ldsm4t(unsigned* r, const void* p) {
    unsigned a = smem_u32(p);
    asm volatile("ldmatrix.sync.aligned.m8n8.x4.trans.shared.b16 {%0,%1,%2,%3}, [%4];"
                 : "=r"(r[0]), "=r"(r[1]), "=r"(r[2]), "=r"(r[3]) : "r"(a));
}
__device__ __forceinline__ void mma16816(float* c, const unsigned* a, unsigned b0, unsigned b1) {
    asm volatile(
        "mma.sync.aligned.m16n8k16.row.col.f32.bf16.bf16.f32 "
        "{%0,%1,%2,%3},{%4,%5,%6,%7},{%8,%9},{%0,%1,%2,%3};"
        : "+f"(c[0]), "+f"(c[1]), "+f"(c[2]), "+f"(c[3])
        : "r"(a[0]), "r"(a[1]), "r"(a[2]), "r"(a[3]), "r"(b0), "r"(b1));
}
__device__ __forceinline__ void split_hilo(float v, __nv_bfloat16& h, __nv_bfloat16& l) {
    h = __float2bfloat16(v);
    l = __float2bfloat16(v - __bfloat162float(h));
}

// ---------------- prep: binarize weights + zero stats ----------------
__global__ void prep_kernel(const float* __restrict__ w1,
                            const float* __restrict__ w2,
                            const float* __restrict__ wd) {
    int i = blockIdx.x * blockDim.x + threadIdx.x;
    constexpr int n1 = L_ * D_ * CB_;
    constexpr int n2 = L_ * CB_ * D_;
    constexpr int n3 = L_ * D_ * 3;
    if (i < n1) {
        float v = w1[i];
        g_w1s[i] = __float2bfloat16(v > 0.f ? 1.f : (v < 0.f ? -1.f : 0.f));
    } else if (i < n1 + n2) {
        float v = w2[i - n1];
        g_w2s[i - n1] = __float2bfloat16(v > 0.f ? 1.f : (v < 0.f ? -1.f : 0.f));
    } else if (i < n1 + n2 + n3) {
        float v = wd[i - n1 - n2];
        g_wds[i - n1 - n2] = v > 0.f ? 1.f : (v < 0.f ? -1.f : 0.f);
    } else if (i < n1 + n2 + n3 + 2 * D_) {
        int j = i - (n1 + n2 + n3);
        if (j < D_) g_sum[j] = 0.f; else g_sumsq[j - D_] = 0.f;
    }
}

// ---------------- fused sign-GEMM (bf16 hi/lo, fp32-exact) ----------------
// Out[b,m,t] = sum_c W[m,c] * act(c)  (+bias, opt prelu+stats, opt affine, opt resid)
// FIRST : conv1 path  (input plain, prelu(a1), stats for BN1, out -> g_z1)
// !FIRST: conv2 path  (input g_z2 with BN2 affine, out -> g_xbuf or d_out(+resid))
constexpr int BM = 128, BN = 128, BK = 32;
constexpr int WPITCH = 40, XPITCH = 136;   // conflict-free pitches

template<bool FIRST, bool RESID>
__global__ void __launch_bounds__(256, 2) gemm_kernel(
    const float* __restrict__ Xext,   // original x (layer0 input / residual src)
    float* __restrict__ Oext,         // d_out (RESID only)
    const float* __restrict__ bias,   // [Cout]
    const float* __restrict__ aptr,   // prelu alpha (FIRST only)
    int layer) {
    constexpr int Cin  = FIRST ? CB_ : D_;
    constexpr int Cout = FIRST ? D_ : CB_;
    const __nv_bfloat16* __restrict__ W =
        (FIRST ? g_w1s : g_w2s) + (size_t)layer * Cin * Cout;
    const float* __restrict__ X = FIRST ? (layer == 0 ? Xext : g_xbuf) : g_z2;
    float* __restrict__ Out = FIRST ? g_z1 : (RESID ? Oext : g_xbuf);

    __shared__ __align__(16) __nv_bfloat16 WS[BM * WPITCH];
    __shared__ __align__(16) __nv_bfloat16 XH[BK * XPITCH];
    __shared__ __align__(16) __nv_bfloat16 XL[BK * XPITCH];

    const int b  = blockIdx.z;
    const int m0 = blockIdx.y * BM;
    const int t0 = blockIdx.x * BN;
    const int tid  = threadIdx.x;
    const int warp = tid >> 5, lane = tid & 31;
    const int wm = (warp & 3) * 32;     // 4 warps along M
    const int wn = (warp >> 2) * 64;    // 2 warps along N

    const float* Xb = X + (size_t)b * Cin * T_ + t0;

    float acc[2][8][4];
    #pragma unroll
    for (int i = 0; i < 2; i++)
        #pragma unroll
        for (int j = 0; j < 8; j++)
            #pragma unroll
            for (int r = 0; r < 4; r++) acc[i][j][r] = 0.f;

    // per-lane ldmatrix.trans address pieces for B
    const int grp = lane >> 3, l8 = lane & 7;
    const int bk_row = (grp & 1) * 8 + l8;
    const int bn_off = (grp >> 1) * 8;

    for (int c0 = 0; c0 < Cin; c0 += BK) {
        __syncthreads();
        // --- W tile [BM x BK] bf16 ---
        {
            const int r  = tid >> 2;
            const int c8 = (tid & 3) * 8;
            *reinterpret_cast<uint4*>(&WS[r * WPITCH + c8]) =
                *reinterpret_cast<const uint4*>(W + (size_t)(m0 + r) * Cin + c0 + c8);
            *reinterpret_cast<uint4*>(&WS[(r + 64) * WPITCH + c8]) =
                *reinterpret_cast<const uint4*>(W + (size_t)(m0 + r + 64) * Cin + c0 + c8);
        }
        // --- X tile [BK x BN]: affine (conv2 path) then hi/lo split ---
        #pragma unroll
        for (int rr = 0; rr < 4; rr++) {
            const int r = warp * 4 + rr;
            const int c = c0 + r;
            float4 v = *reinterpret_cast<const float4*>(Xb + (size_t)c * T_ + lane * 4);
            if (!FIRST) {
                const float s = g_scale[c], sh = g_shift[c];
                v.x = fmaf(s, v.x, sh); v.y = fmaf(s, v.y, sh);
                v.z = fmaf(s, v.z, sh); v.w = fmaf(s, v.w, sh);
            }
            __nv_bfloat16 h0, h1, h2, h3, l0, l1, l2, l3;
            split_hilo(v.x, h0, l0); split_hilo(v.y, h1, l1);
            split_hilo(v.z, h2, l2); split_hilo(v.w, h3, l3);
            __nv_bfloat162* ph = reinterpret_cast<__nv_bfloat162*>(&XH[r * XPITCH + lane * 4]);
            __nv_bfloat162* pl = reinterpret_cast<__nv_bfloat162*>(&XL[r * XPITCH + lane * 4]);
            __nv_bfloat162 t;
            t.x = h0; t.y = h1; ph[0] = t;
            t.x = h2; t.y = h3; ph[1] = t;
            t.x = l0; t.y = l1; pl[0] = t;
            t.x = l2; t.y = l3; pl[1] = t;
        }
        __syncthreads();
        // --- compute: K' = 2*BK (hi pass + lo pass share W) ---
        #pragma unroll
        for (int kk = 0; kk < 2; kk++) {
            const int k0 = kk * 16;
            unsigned a[2][4];
            #pragma unroll
            for (int mf = 0; mf < 2; mf++)
                ldsm4(a[mf], &WS[(wm + mf * 16 + (lane & 15)) * WPITCH + k0 + (lane >> 4) * 8]);
            #pragma unroll
            for (int nb = 0; nb < 4; nb++) {
                unsigned bq[4];
                const int baddr = (k0 + bk_row) * XPITCH + wn + nb * 16 + bn_off;
                ldsm4t(bq, &XH[baddr]);
                #pragma unroll
                for (int mf = 0; mf < 2; mf++) {
                    mma16816(acc[mf][2 * nb],     a[mf], bq[0], bq[1]);
                    mma16816(acc[mf][2 * nb + 1], a[mf], bq[2], bq[3]);
                }
                ldsm4t(bq, &XL[baddr]);
                #pragma unroll
                for (int mf = 0; mf < 2; mf++) {
                    mma16816(acc[mf][2 * nb],     a[mf], bq[0], bq[1]);
                    mma16816(acc[mf][2 * nb + 1], a[mf], bq[2], bq[3]);
                }
            }
        }
    }

    // --- epilogue: bias (+prelu+stats | +resid), write fp32 ---
    float av = 0.f;
    if (FIRST) av = __ldg(aptr);
    #pragma unroll
    for (int mf = 0; mf < 2; mf++) {
        #pragma unroll
        for (int half = 0; half < 2; half++) {
            const int row = m0 + wm + mf * 16 + (lane >> 2) + half * 8;
            const float bv = __ldg(bias + row);
            float* orow = Out + (size_t)b * Cout * T_ + (size_t)row * T_ + t0;
            const float* rrow = RESID ? (Xext + (size_t)b * Cout * T_ + (size_t)row * T_ + t0)
                                      : nullptr;
            float ps = 0.f, pss = 0.f;
            #pragma unroll
            for (int nf = 0; nf < 8; nf++) {
                const int col = wn + nf * 8 + (lane & 3) * 2;
                float v0 = acc[mf][nf][half * 2 + 0] + bv;
                float v1 = acc[mf][nf][half * 2 + 1] + bv;
                if (FIRST) {
                    v0 = v0 >= 0.f ? v0 : av * v0;
                    v1 = v1 >= 0.f ? v1 : av * v1;
                    ps += v0 + v1;
                    pss += fmaf(v0, v0, v1 * v1);
                }
                if (RESID) {
                    const float2 rv = *reinterpret_cast<const float2*>(rrow + col);
                    v0 += rv.x; v1 += rv.y;
                }
                float2 o2; o2.x = v0; o2.y = v1;
                *reinterpret_cast<float2*>(orow + col) = o2;
            }
            if (FIRST) {  // quad reduce (lanes sharing this row), then global red
                ps  += __shfl_xor_sync(0xffffffffu, ps, 1);
                ps  += __shfl_xor_sync(0xffffffffu, ps, 2);
                pss += __shfl_xor_sync(0xffffffffu, pss, 1);
                pss += __shfl_xor_sync(0xffffffffu, pss, 2);
                if ((lane & 3) == 0) {
                    atomicAdd(&g_sum[row], ps);
                    atomicAdd(&g_sumsq[row], pss);
                }
            }
        }
    }
}

// ---------------- BN finalize: scale/shift, re-zero accumulators ----------------
__global__ void bnfin_kernel(const float* __restrict__ gch,
                             const float* __restrict__ bech) {
    int i = threadIdx.x;
    if (i < D_) {
        const float invN = 1.f / (float)N_BT;
        float mean = g_sum[i] * invN;
        float var  = g_sumsq[i] * invN - mean * mean;
        float s = __ldg(gch + i) * rsqrtf(var + EPS_);
        g_scale[i] = s;
        g_shift[i] = __ldg(bech + i) - mean * s;
        g_sum[i] = 0.f;
        g_sumsq[i] = 0.f;
    }
}

// ---------------- depthwise dilated causal conv (BN1 affine fused) ----------------
__global__ void __launch_bounds__(256) dwconv_kernel(const float* __restrict__ bdl,
                                                     const float* __restrict__ aptr,
                                                     int layer) {
    const int d = blockIdx.y, b = blockIdx.z;
    const int dil = 1 << layer;
    const float* __restrict__ zin = g_z1 + ((size_t)b * D_ + d) * T_;
    float* __restrict__ zo = g_z2 + ((size_t)b * D_ + d) * T_;
    const float w0 = g_wds[(layer * D_ + d) * 3 + 0];
    const float w1 = g_wds[(layer * D_ + d) * 3 + 1];
    const float w2 = g_wds[(layer * D_ + d) * 3 + 2];
    const float s = g_scale[d], sh = g_shift[d];
    const float bb = __ldg(bdl + d);
    const float av = __ldg(aptr);
    const int t0 = blockIdx.x * 1024 + threadIdx.x * 4;

    float vv[4];
    float ps = 0.f, pss = 0.f;
    #pragma unroll
    for (int j = 0; j < 4; j++) {
        const int t = t0 + j;
        float acc = bb;
        const int tm2 = t - 2 * dil, tm1 = t - dil;
        if (tm2 >= 0) acc = fmaf(w0, fmaf(s, __ldg(zin + tm2), sh), acc);
        if (tm1 >= 0) acc = fmaf(w1, fmaf(s, __ldg(zin + tm1), sh), acc);
        acc = fmaf(w2, fmaf(s, __ldg(zin + t), sh), acc);
        float v = acc >= 0.f ? acc : av * acc;
        vv[j] = v;
        ps += v;
        pss = fmaf(v, v, pss);
    }
    float4 o4; o4.x = vv[0]; o4.y = vv[1]; o4.z = vv[2]; o4.w = vv[3];
    *reinterpret_cast<float4*>(zo + t0) = o4;

    // block reduce (whole CTA = one channel d)
    #pragma unroll
    for (int o = 16; o; o >>= 1) {
        ps  += __shfl_down_sync(0xffffffffu, ps, o);
        pss += __shfl_down_sync(0xffffffffu, pss, o);
    }
    __shared__ float ss[8], sq[8];
    const int warp = threadIdx.x >> 5, lane = threadIdx.x & 31;
    if (lane == 0) { ss[warp] = ps; sq[warp] = pss; }
    __syncthreads();
    if (warp == 0) {
        ps  = lane < 8 ? ss[lane] : 0.f;
        pss = lane < 8 ? sq[lane] : 0.f;
        #pragma unroll
        for (int o = 4; o; o >>= 1) {
            ps  += __shfl_down_sync(0xffffffffu, ps, o);
            pss += __shfl_down_sync(0xffffffffu, pss, o);
        }
        if (lane == 0) {
            atomicAdd(&g_sum[d], ps);
            atomicAdd(&g_sumsq[d], pss);
        }
    }
}

// ---------------- launch ----------------
extern "C" void kernel_launch(void* const* d_in, const int* in_sizes, int n_in,
                              void* d_out, int out_size) {
    (void)in_sizes; (void)n_in; (void)out_size;
    const float* x   = (const float*)d_in[0];
    const float* w1  = (const float*)d_in[1];
    const float* b1  = (const float*)d_in[2];
    const float* a1  = (const float*)d_in[3];
    const float* g1  = (const float*)d_in[4];
    const float* be1 = (const float*)d_in[5];
    const float* wd  = (const float*)d_in[6];
    const float* bd  = (const float*)d_in[7];
    const float* a2  = (const float*)d_in[8];
    const float* g2  = (const float*)d_in[9];
    const float* be2 = (const float*)d_in[10];
    const float* w2  = (const float*)d_in[11];  // unused slot order check: w2 weights
    const float* b2  = (const float*)d_in[12];
    float* out = (float*)d_out;

    constexpr int prep_total = L_ * D_ * CB_ + L_ * CB_ * D_ + L_ * D_ * 3 + 2 * D_;
    prep_kernel<<<(prep_total + 255) / 256, 256>>>(w1, w2, wd);

    dim3 gg1(T_ / BN, D_ / BM, B_);    // 32 x 4 x 16
    dim3 gg2(T_ / BN, CB_ / BM, B_);   // 32 x 2 x 16
    dim3 gdw(T_ / 1024, D_, B_);       // 4 x 512 x 16

    for (int i = 0; i < L_; i++) {
        gemm_kernel<true, false><<<gg1, 256>>>(x, nullptr, b1 + i * D_, a1 + i, i);
        bnfin_kernel<<<1, D_>>>(g1 + i * D_, be1 + i * D_);
        dwconv_kernel<<<gdw, 256>>>(bd + i * D_, a2 + i, i);
        bnfin_kernel<<<1, D_>>>(g2 + i * D_, be2 + i * D_);
        if (i < L_ - 1)
            gemm_kernel<false, false><<<gg2, 256>>>(nullptr, nullptr, b2 + i * CB_, nullptr, i);
        else
            gemm_kernel<false, true><<<gg2, 256>>>(x, out, b2 + i * CB_, nullptr, i);
    }
}

// round 8
// speedup vs baseline: 1.1299x; 1.1299x over previous
#include <cuda_runtime.h>
#include <cuda_bf16.h>

// ---------------- problem constants ----------------
constexpr int L_  = 4;
constexpr int CB_ = 256;
constexpr int D_  = 512;
constexpr int B_  = 16;
constexpr int T_  = 4096;
constexpr int N_BT = B_ * T_;
constexpr float EPS_ = 1e-5f;

// ---------------- device scratch ----------------
__device__ float g_xbuf[(size_t)B_ * CB_ * T_];
__device__ float g_z1[(size_t)B_ * D_ * T_];
__device__ float g_z2[(size_t)B_ * D_ * T_];
__device__ __align__(16) __nv_bfloat16 g_w1s[L_ * D_ * CB_];
__device__ __align__(16) __nv_bfloat16 g_w2s[L_ * CB_ * D_];
__device__ float g_wds[L_ * D_ * 3];
__device__ float g_sum[D_];
__device__ float g_sumsq[D_];
__device__ float g_scale[D_];
__device__ float g_shift[D_];
__device__ float2 g_ss[D_];

// ---------------- PTX helpers ----------------
__device__ __forceinline__ unsigned smem_u32(const void* p) {
    return (unsigned)__cvta_generic_to_shared(p);
}
__device__ __forceinline__ void ldsm4(unsigned* r, const void* p) {
    unsigned a = smem_u32(p);
    asm volatile("ldmatrix.sync.aligned.m8n8.x4.shared.b16 {%0,%1,%2,%3}, [%4];"
                 : "=r"(r[0]), "=r"(r[1]), "=r"(r[2]), "=r"(r[3]) : "r"(a));
}
__device__ __forceinline__ void ldsm4t(unsigned* r, const void* p) {
    unsigned a = smem_u32(p);
    asm volatile("ldmatrix.sync.aligned.m8n8.x4.trans.shared.b16 {%0,%1,%2,%3}, [%4];"
                 : "=r"(r[0]), "=r"(r[1]), "=r"(r[2]), "=r"(r[3]) : "r"(a));
}
__device__ __forceinline__ void mma16816(float* c, const unsigned* a, unsigned b0, unsigned b1) {
    asm volatile(
        "mma.sync.aligned.m16n8k16.row.col.f32.bf16.bf16.f32 "
        "{%0,%1,%2,%3},{%4,%5,%6,%7},{%8,%9},{%0,%1,%2,%3};"
        : "+f"(c[0]), "+f"(c[1]), "+f"(c[2]), "+f"(c[3])
        : "r"(a[0]), "r"(a[1]), "r"(a[2]), "r"(a[3]), "r"(b0), "r"(b1));
}
__device__ __forceinline__ void split_hilo(float v, __nv_bfloat16& h, __nv_bfloat16& l) {
    h = __float2bfloat16(v);
    l = __float2bfloat16(v - __bfloat162float(h));
}

// ---------------- prep ----------------
__global__ void prep_kernel(const float* __restrict__ w1,
                            const float* __restrict__ w2,
                            const float* __restrict__ wd) {
    int i = blockIdx.x * blockDim.x + threadIdx.x;
    constexpr int n1 = L_ * D_ * CB_;
    constexpr int n2 = L_ * CB_ * D_;
    constexpr int n3 = L_ * D_ * 3;
    if (i < n1) {
        float v = w1[i];
        g_w1s[i] = __float2bfloat16(v > 0.f ? 1.f : (v < 0.f ? -1.f : 0.f));
    } else if (i < n1 + n2) {
        float v = w2[i - n1];
        g_w2s[i - n1] = __float2bfloat16(v > 0.f ? 1.f : (v < 0.f ? -1.f : 0.f));
    } else if (i < n1 + n2 + n3) {
        float v = wd[i - n1 - n2];
        g_wds[i - n1 - n2] = v > 0.f ? 1.f : (v < 0.f ? -1.f : 0.f);
    } else if (i < n1 + n2 + n3 + 2 * D_) {
        int j = i - (n1 + n2 + n3);
        if (j < D_) g_sum[j] = 0.f; else g_sumsq[j - D_] = 0.f;
    }
}

// ---------------- fused sign-GEMM, double-buffered ----------------
constexpr int BM = 128, BN = 128, BK = 32;
constexpr int WPITCH = 40, XPITCH = 136;
constexpr int WS_ELEMS = BM * WPITCH;      // per buffer
constexpr int XT_ELEMS = BK * XPITCH;      // per buffer
constexpr size_t GEMM_SMEM = (size_t)(2 * WS_ELEMS + 4 * XT_ELEMS) * sizeof(__nv_bfloat16);

template<bool FIRST, bool RESID>
__global__ void __launch_bounds__(256, 2) gemm_kernel(
    const float* __restrict__ Xext,
    float* __restrict__ Oext,
    const float* __restrict__ bias,
    const float* __restrict__ aptr,
    int layer) {
    constexpr int Cin  = FIRST ? CB_ : D_;
    constexpr int Cout = FIRST ? D_ : CB_;
    constexpr int NITER = Cin / BK;
    const __nv_bfloat16* __restrict__ W =
        (FIRST ? g_w1s : g_w2s) + (size_t)layer * Cin * Cout;
    const float* __restrict__ X = FIRST ? (layer == 0 ? Xext : g_xbuf) : g_z2;
    float* __restrict__ Out = FIRST ? g_z1 : (RESID ? Oext : g_xbuf);

    extern __shared__ __align__(16) char sm_raw[];
    __nv_bfloat16* WS = reinterpret_cast<__nv_bfloat16*>(sm_raw);
    __nv_bfloat16* XH = WS + 2 * WS_ELEMS;
    __nv_bfloat16* XL = XH + 2 * XT_ELEMS;

    const int b  = blockIdx.z;
    const int m0 = blockIdx.y * BM;
    const int t0 = blockIdx.x * BN;
    const int tid  = threadIdx.x;
    const int warp = tid >> 5, lane = tid & 31;
    const int wm = (warp & 3) * 32;
    const int wn = (warp >> 2) * 64;

    const float* Xb = X + (size_t)b * Cin * T_ + t0;
    const int wrow = tid >> 2;
    const int wcol = (tid & 3) * 8;

    float acc[2][8][4];
    #pragma unroll
    for (int i = 0; i < 2; i++)
        #pragma unroll
        for (int j = 0; j < 8; j++)
            #pragma unroll
            for (int r = 0; r < 4; r++) acc[i][j][r] = 0.f;

    const int grp = lane >> 3, l8 = lane & 7;
    const int bk_row = (grp & 1) * 8 + l8;
    const int bn_off = (grp >> 1) * 8;

    uint4 wreg0, wreg1;
    float4 xreg[4];
    float2 ssreg[4];

    auto issue_loads = [&](int c0) {
        wreg0 = *reinterpret_cast<const uint4*>(W + (size_t)(m0 + wrow) * Cin + c0 + wcol);
        wreg1 = *reinterpret_cast<const uint4*>(W + (size_t)(m0 + wrow + 64) * Cin + c0 + wcol);
        #pragma unroll
        for (int rr = 0; rr < 4; rr++) {
            const int c = c0 + warp * 4 + rr;
            xreg[rr] = *reinterpret_cast<const float4*>(Xb + (size_t)c * T_ + lane * 4);
            if (!FIRST) ssreg[rr] = g_ss[c];
        }
    };
    auto commit = [&](int p) {
        *reinterpret_cast<uint4*>(&WS[p * WS_ELEMS + wrow * WPITCH + wcol]) = wreg0;
        *reinterpret_cast<uint4*>(&WS[p * WS_ELEMS + (wrow + 64) * WPITCH + wcol]) = wreg1;
        #pragma unroll
        for (int rr = 0; rr < 4; rr++) {
            const int r = warp * 4 + rr;
            float4 v = xreg[rr];
            if (!FIRST) {
                const float s = ssreg[rr].x, sh = ssreg[rr].y;
                v.x = fmaf(s, v.x, sh); v.y = fmaf(s, v.y, sh);
                v.z = fmaf(s, v.z, sh); v.w = fmaf(s, v.w, sh);
            }
            __nv_bfloat16 h0, h1, h2, h3, l0, l1, l2, l3;
            split_hilo(v.x, h0, l0); split_hilo(v.y, h1, l1);
            split_hilo(v.z, h2, l2); split_hilo(v.w, h3, l3);
            __nv_bfloat162* ph = reinterpret_cast<__nv_bfloat162*>(
                &XH[p * XT_ELEMS + r * XPITCH + lane * 4]);
            __nv_bfloat162* pl = reinterpret_cast<__nv_bfloat162*>(
                &XL[p * XT_ELEMS + r * XPITCH + lane * 4]);
            __nv_bfloat162 t;
            t.x = h0; t.y = h1; ph[0] = t;
            t.x = h2; t.y = h3; ph[1] = t;
            t.x = l0; t.y = l1; pl[0] = t;
            t.x = l2; t.y = l3; pl[1] = t;
        }
    };
    auto compute = [&](int p) {
        #pragma unroll
        for (int kk = 0; kk < 2; kk++) {
            const int k0 = kk * 16;
            unsigned a[2][4];
            #pragma unroll
            for (int mf = 0; mf < 2; mf++)
                ldsm4(a[mf], &WS[p * WS_ELEMS + (wm + mf * 16 + (lane & 15)) * WPITCH +
                                 k0 + (lane >> 4) * 8]);
            #pragma unroll
            for (int nb = 0; nb < 4; nb++) {
                unsigned bq[4];
                const int baddr = (k0 + bk_row) * XPITCH + wn + nb * 16 + bn_off;
                ldsm4t(bq, &XH[p * XT_ELEMS + baddr]);
                #pragma unroll
                for (int mf = 0; mf < 2; mf++) {
                    mma16816(acc[mf][2 * nb],     a[mf], bq[0], bq[1]);
                    mma16816(acc[mf][2 * nb + 1], a[mf], bq[2], bq[3]);
                }
                ldsm4t(bq, &XL[p * XT_ELEMS + baddr]);
                #pragma unroll
                for (int mf = 0; mf < 2; mf++) {
                    mma16816(acc[mf][2 * nb],     a[mf], bq[0], bq[1]);
                    mma16816(acc[mf][2 * nb + 1], a[mf], bq[2], bq[3]);
                }
            }
        }
    };

    issue_loads(0);
    commit(0);
    __syncthreads();
    int p = 0;
    #pragma unroll 1
    for (int it = 0; it < NITER; ++it) {
        if (it + 1 < NITER) issue_loads((it + 1) * BK);
        compute(p);
        if (it + 1 < NITER) {
            commit(p ^ 1);
            __syncthreads();
        }
        p ^= 1;
    }

    // --- epilogue ---
    float av = 0.f;
    if (FIRST) av = __ldg(aptr);
    #pragma unroll
    for (int mf = 0; mf < 2; mf++) {
        #pragma unroll
        for (int half = 0; half < 2; half++) {
            const int row = m0 + wm + mf * 16 + (lane >> 2) + half * 8;
            const float bv = __ldg(bias + row);
            float* orow = Out + (size_t)b * Cout * T_ + (size_t)row * T_ + t0;
            const float* rrow = RESID ? (Xext + (size_t)b * Cout * T_ + (size_t)row * T_ + t0)
                                      : nullptr;
            float ps = 0.f, pss = 0.f;
            #pragma unroll
            for (int nf = 0; nf < 8; nf++) {
                const int col = wn + nf * 8 + (lane & 3) * 2;
                float v0 = acc[mf][nf][half * 2 + 0] + bv;
                float v1 = acc[mf][nf][half * 2 + 1] + bv;
                if (FIRST) {
                    v0 = v0 >= 0.f ? v0 : av * v0;
                    v1 = v1 >= 0.f ? v1 : av * v1;
                    ps += v0 + v1;
                    pss += fmaf(v0, v0, v1 * v1);
                }
                if (RESID) {
                    const float2 rv = *reinterpret_cast<const float2*>(rrow + col);
                    v0 += rv.x; v1 += rv.y;
                }
                float2 o2; o2.x = v0; o2.y = v1;
                *reinterpret_cast<float2*>(orow + col) = o2;
            }
            if (FIRST) {
                ps  += __shfl_xor_sync(0xffffffffu, ps, 1);
                ps  += __shfl_xor_sync(0xffffffffu, ps, 2);
                pss += __shfl_xor_sync(0xffffffffu, pss, 1);
                pss += __shfl_xor_sync(0xffffffffu, pss, 2);
                if ((lane & 3) == 0) {
                    atomicAdd(&g_sum[row], ps);
                    atomicAdd(&g_sumsq[row], pss);
                }
            }
        }
    }
}

// ---------------- BN finalize ----------------
__global__ void bnfin_kernel(const float* __restrict__ gch,
                             const float* __restrict__ bech) {
    int i = threadIdx.x;
    if (i < D_) {
        const float invN = 1.f / (float)N_BT;
        float mean = g_sum[i] * invN;
        float var  = g_sumsq[i] * invN - mean * mean;
        float s = __ldg(gch + i) * rsqrtf(var + EPS_);
        float sh = __ldg(bech + i) - mean * s;
        g_scale[i] = s;
        g_shift[i] = sh;
        g_ss[i] = make_float2(s, sh);
        g_sum[i] = 0.f;
        g_sumsq[i] = 0.f;
    }
}

// ---------------- depthwise dilated causal conv (smem-staged) ----------------
template<int DIL>
__global__ void __launch_bounds__(256) dwconv_kernel(const float* __restrict__ bdl,
                                                     const float* __restrict__ aptr,
                                                     int layer) {
    const int d = blockIdx.y, b = blockIdx.z;
    const int tb = blockIdx.x * 1024;
    __shared__ float s[16 + 1024];
    const float* __restrict__ zin = g_z1 + ((size_t)b * D_ + d) * T_;
    float* __restrict__ zo = g_z2 + ((size_t)b * D_ + d) * T_;
    const float sc = g_scale[d], sh = g_shift[d];

    // main body: affined values, coalesced float4
    {
        float4 v = *reinterpret_cast<const float4*>(zin + tb + threadIdx.x * 4);
        float4 w;
        w.x = fmaf(sc, v.x, sh); w.y = fmaf(sc, v.y, sh);
        w.z = fmaf(sc, v.z, sh); w.w = fmaf(sc, v.w, sh);
        *reinterpret_cast<float4*>(&s[16 + threadIdx.x * 4]) = w;
    }
    // halo: 16 elements before tb (0 if global t < 0 -> causal zero pad)
    if (threadIdx.x < 4) {
        const int base = tb - 16 + threadIdx.x * 4;
        float4 w;
        w.x = (base + 0) >= 0 ? fmaf(sc, zin[base + 0], sh) : 0.f;
        w.y = (base + 1) >= 0 ? fmaf(sc, zin[base + 1], sh) : 0.f;
        w.z = (base + 2) >= 0 ? fmaf(sc, zin[base + 2], sh) : 0.f;
        w.w = (base + 3) >= 0 ? fmaf(sc, zin[base + 3], sh) : 0.f;
        *reinterpret_cast<float4*>(&s[threadIdx.x * 4]) = w;
    }
    __syncthreads();

    const float w0 = g_wds[(layer * D_ + d) * 3 + 0];
    const float w1 = g_wds[(layer * D_ + d) * 3 + 1];
    const float w2 = g_wds[(layer * D_ + d) * 3 + 2];
    const float bb = __ldg(bdl + d);
    const float av = __ldg(aptr);

    const int t0 = threadIdx.x * 4;
    float r[20];
    #pragma unroll
    for (int q = 0; q < 5; q++)
        *reinterpret_cast<float4*>(&r[q * 4]) =
            *reinterpret_cast<const float4*>(&s[t0 + q * 4]);

    float vv[4];
    float ps = 0.f, pss = 0.f;
    #pragma unroll
    for (int j = 0; j < 4; j++) {
        float acc = bb;
        acc = fmaf(w0, r[16 + j - 2 * DIL], acc);
        acc = fmaf(w1, r[16 + j - DIL], acc);
        acc = fmaf(w2, r[16 + j], acc);
        float v = acc >= 0.f ? acc : av * acc;
        vv[j] = v;
        ps += v;
        pss = fmaf(v, v, pss);
    }
    float4 o4; o4.x = vv[0]; o4.y = vv[1]; o4.z = vv[2]; o4.w = vv[3];
    *reinterpret_cast<float4*>(zo + tb + t0) = o4;

    #pragma unroll
    for (int o = 16; o; o >>= 1) {
        ps  += __shfl_down_sync(0xffffffffu, ps, o);
        pss += __shfl_down_sync(0xffffffffu, pss, o);
    }
    __shared__ float ssum[8], ssq[8];
    const int warp = threadIdx.x >> 5, lane = threadIdx.x & 31;
    if (lane == 0) { ssum[warp] = ps; ssq[warp] = pss; }
    __syncthreads();
    if (warp == 0) {
        ps  = lane < 8 ? ssum[lane] : 0.f;
        pss = lane < 8 ? ssq[lane] : 0.f;
        #pragma unroll
        for (int o = 4; o; o >>= 1) {
            ps  += __shfl_down_sync(0xffffffffu, ps, o);
            pss += __shfl_down_sync(0xffffffffu, pss, o);
        }
        if (lane == 0) {
            atomicAdd(&g_sum[d], ps);
            atomicAdd(&g_sumsq[d], pss);
        }
    }
}

// ---------------- launch ----------------
extern "C" void kernel_launch(void* const* d_in, const int* in_sizes, int n_in,
                              void* d_out, int out_size) {
    (void)in_sizes; (void)n_in; (void)out_size;
    const float* x   = (const float*)d_in[0];
    const float* w1  = (const float*)d_in[1];
    const float* b1  = (const float*)d_in[2];
    const float* a1  = (const float*)d_in[3];
    const float* g1  = (const float*)d_in[4];
    const float* be1 = (const float*)d_in[5];
    const float* wd  = (const float*)d_in[6];
    const float* bd  = (const float*)d_in[7];
    const float* a2  = (const float*)d_in[8];
    const float* g2  = (const float*)d_in[9];
    const float* be2 = (const float*)d_in[10];
    const float* w2  = (const float*)d_in[11];
    const float* b2  = (const float*)d_in[12];
    float* out = (float*)d_out;

    static bool attr_done = false;
    if (!attr_done) {
        cudaFuncSetAttribute(gemm_kernel<true, false>,
                             cudaFuncAttributeMaxDynamicSharedMemorySize, (int)GEMM_SMEM);
        cudaFuncSetAttribute(gemm_kernel<false, false>,
                             cudaFuncAttributeMaxDynamicSharedMemorySize, (int)GEMM_SMEM);
        cudaFuncSetAttribute(gemm_kernel<false, true>,
                             cudaFuncAttributeMaxDynamicSharedMemorySize, (int)GEMM_SMEM);
        attr_done = true;
    }

    constexpr int prep_total = L_ * D_ * CB_ + L_ * CB_ * D_ + L_ * D_ * 3 + 2 * D_;
    prep_kernel<<<(prep_total + 255) / 256, 256>>>(w1, w2, wd);

    dim3 gg1(T_ / BN, D_ / BM, B_);
    dim3 gg2(T_ / BN, CB_ / BM, B_);
    dim3 gdw(T_ / 1024, D_, B_);

    for (int i = 0; i < L_; i++) {
        gemm_kernel<true, false><<<gg1, 256, GEMM_SMEM>>>(x, nullptr, b1 + i * D_, a1 + i, i);
        bnfin_kernel<<<1, D_>>>(g1 + i * D_, be1 + i * D_);
        switch (i) {
            case 0: dwconv_kernel<1><<<gdw, 256>>>(bd + i * D_, a2 + i, i); break;
            case 1: dwconv_kernel<2><<<gdw, 256>>>(bd + i * D_, a2 + i, i); break;
            case 2: dwconv_kernel<4><<<gdw, 256>>>(bd + i * D_, a2 + i, i); break;
            default: dwconv_kernel<8><<<gdw, 256>>>(bd + i * D_, a2 + i, i); break;
        }
        bnfin_kernel<<<1, D_>>>(g2 + i * D_, be2 + i * D_);
        if (i < L_ - 1)
            gemm_kernel<false, false><<<gg2, 256, GEMM_SMEM>>>(nullptr, nullptr, b2 + i * CB_, nullptr, i);
        else
            gemm_kernel<false, true><<<gg2, 256, GEMM_SMEM>>>(x, out, b2 + i * CB_, nullptr, i);
    }
}